// round 2
// baseline (speedup 1.0000x reference)
#include <cuda_runtime.h>

// DynamicHead: per-sample grouped 1x1 conv.
// f:      [B=8, C=400, H=128, W=128] fp32
// kernel: [B=8, N=50, CPG=8, 1, 1]   fp32
// out:    [B=8, N=50, H=128, W=128]  fp32
// out[b][n][hw] = sum_{c<8} f[b][n*8+c][hw] * kernel[b][n][c]

#define B_   8
#define N_   50
#define CPG_ 8
#define HW_  (128 * 128)        // 16384
#define HW4_ (HW_ / 4)          // 4096 float4 per plane
#define CHUNKS_ 4               // hw chunks per (b,n)
#define TPB_ 256
#define ITERS_ (HW4_ / CHUNKS_ / TPB_)  // 4

__global__ __launch_bounds__(TPB_)
void dynhead_1x1_kernel(const float* __restrict__ f,
                        const float* __restrict__ kern,
                        float* __restrict__ out) {
    const int bn    = blockIdx.x >> 2;      // 0..399
    const int chunk = blockIdx.x & (CHUNKS_ - 1);
    const int b = bn / N_;
    const int n = bn - b * N_;

    // Hoist the 8 group weights into registers (L1-broadcast; 12.8KB total).
    float w[CPG_];
    const float* kp = kern + (long)bn * CPG_;
#pragma unroll
    for (int c = 0; c < CPG_; c++) w[c] = __ldg(kp + c);

    // Base of this (b,n) group's 8 input channel planes.
    const float4* __restrict__ fin =
        (const float4*)(f + ((long)b * 400 + (long)n * CPG_) * HW_);
    float4* __restrict__ o = (float4*)(out + (long)bn * HW_);

    const int base = chunk * (HW4_ / CHUNKS_) + threadIdx.x;

#pragma unroll
    for (int i = 0; i < ITERS_; i++) {
        const int idx = base + i * TPB_;
        float4 acc = make_float4(0.f, 0.f, 0.f, 0.f);
#pragma unroll
        for (int c = 0; c < CPG_; c++) {
            const float4 v = fin[(long)c * HW4_ + idx];
            acc.x = fmaf(w[c], v.x, acc.x);
            acc.y = fmaf(w[c], v.y, acc.y);
            acc.z = fmaf(w[c], v.z, acc.z);
            acc.w = fmaf(w[c], v.w, acc.w);
        }
        o[idx] = acc;
    }
}

extern "C" void kernel_launch(void* const* d_in, const int* in_sizes, int n_in,
                              void* d_out, int out_size) {
    const float* f    = (const float*)d_in[0];
    const float* kern = (const float*)d_in[1];
    float* out        = (float*)d_out;

    dim3 grid(B_ * N_ * CHUNKS_);   // 1600 CTAs
    dynhead_1x1_kernel<<<grid, TPB_>>>(f, kern, out);
}

// round 3
// speedup vs baseline: 1.0081x; 1.0081x over previous
#include <cuda_runtime.h>

// DynamicHead: per-sample grouped 1x1 conv (KERNEL_SIZE=1, PAD=0).
// f:      [B=8, C=400, H=128, W=128] fp32
// kernel: [B=8, N=50, CPG=8, 1, 1]   fp32
// out:    [B=8, N=50, H=128, W=128]  fp32
// out[b][n][hw] = sum_{c<8} f[b][n*8+c][hw] * kernel[b][n][c]
//
// Pure HBM-bound (236 MB, AI ~0.44 FLOP/B). Strategy: single resident wave
// (grid = SMs*8 CTAs of 256 thr) + grid-stride loop over flattened float4
// output index -> no wave-quantization tail.

#define N_      50
#define HW4_    4096                      // 128*128/4 float4 per plane
#define TOTAL4  (8 * 50 * HW4_)           // 1,638,400 output float4
#define TPB_    256

__global__ __launch_bounds__(TPB_)
void dynhead_1x1_gs(const float4* __restrict__ f4,
                    const float* __restrict__ kern,
                    float4* __restrict__ o4) {
    const int stride = gridDim.x * TPB_;
    for (int idx = blockIdx.x * TPB_ + threadIdx.x; idx < TOTAL4; idx += stride) {
        const int bn  = idx >> 12;            // idx / 4096  (0..399)
        const int pos = idx & (HW4_ - 1);
        const int b = bn / N_;                // magic-mul division
        const int n = bn - b * N_;

        // 8 group weights: warp-uniform (whole warp shares bn), L1 broadcast.
        const float* kp = kern + bn * 8;
        float w0 = __ldg(kp + 0), w1 = __ldg(kp + 1);
        float w2 = __ldg(kp + 2), w3 = __ldg(kp + 3);
        float w4 = __ldg(kp + 4), w5 = __ldg(kp + 5);
        float w6 = __ldg(kp + 6), w7 = __ldg(kp + 7);

        // 8 input channel planes for this group; 8 independent LDG.128 (MLP=8).
        const float4* fp = f4 + (((b * 400 + n * 8) << 12) + pos);
        const float4 v0 = fp[0 * HW4_];
        const float4 v1 = fp[1 * HW4_];
        const float4 v2 = fp[2 * HW4_];
        const float4 v3 = fp[3 * HW4_];
        const float4 v4 = fp[4 * HW4_];
        const float4 v5 = fp[5 * HW4_];
        const float4 v6 = fp[6 * HW4_];
        const float4 v7 = fp[7 * HW4_];

        float4 acc;
        acc.x = v0.x * w0; acc.y = v0.y * w0; acc.z = v0.z * w0; acc.w = v0.w * w0;
        acc.x = fmaf(w1, v1.x, acc.x); acc.y = fmaf(w1, v1.y, acc.y);
        acc.z = fmaf(w1, v1.z, acc.z); acc.w = fmaf(w1, v1.w, acc.w);
        acc.x = fmaf(w2, v2.x, acc.x); acc.y = fmaf(w2, v2.y, acc.y);
        acc.z = fmaf(w2, v2.z, acc.z); acc.w = fmaf(w2, v2.w, acc.w);
        acc.x = fmaf(w3, v3.x, acc.x); acc.y = fmaf(w3, v3.y, acc.y);
        acc.z = fmaf(w3, v3.z, acc.z); acc.w = fmaf(w3, v3.w, acc.w);
        acc.x = fmaf(w4, v4.x, acc.x); acc.y = fmaf(w4, v4.y, acc.y);
        acc.z = fmaf(w4, v4.z, acc.z); acc.w = fmaf(w4, v4.w, acc.w);
        acc.x = fmaf(w5, v5.x, acc.x); acc.y = fmaf(w5, v5.y, acc.y);
        acc.z = fmaf(w5, v5.z, acc.z); acc.w = fmaf(w5, v5.w, acc.w);
        acc.x = fmaf(w6, v6.x, acc.x); acc.y = fmaf(w6, v6.y, acc.y);
        acc.z = fmaf(w6, v6.z, acc.z); acc.w = fmaf(w6, v6.w, acc.w);
        acc.x = fmaf(w7, v7.x, acc.x); acc.y = fmaf(w7, v7.y, acc.y);
        acc.z = fmaf(w7, v7.z, acc.z); acc.w = fmaf(w7, v7.w, acc.w);

        o4[idx] = acc;
    }
}

extern "C" void kernel_launch(void* const* d_in, const int* in_sizes, int n_in,
                              void* d_out, int out_size) {
    const float4* f4  = (const float4*)d_in[0];
    const float* kern = (const float*)d_in[1];
    float4* o4        = (float4*)d_out;

    // Exactly one resident wave: 8 CTAs/SM (256 thr -> 2048/SM cap).
    // Attribute query is host-side only; it runs at capture time and is
    // baked into the graph (not replayed).
    int sm = 148;
    cudaDeviceGetAttribute(&sm, cudaDevAttrMultiProcessorCount, 0);
    dim3 grid(sm * 8);
    dynhead_1x1_gs<<<grid, TPB_>>>(f4, kern, o4);
}